// round 11
// baseline (speedup 1.0000x reference)
#include <cuda_runtime.h>
#include <cuda_fp16.h>
#include <cstdint>

// HypercomplexLinear via DFT-4 diagonalization + fp16 mma.sync m16n8k16,
// FULLY FUSED: each CTA (128 M x 64 o, 512 threads) accumulates a0, a2, P, Q
// for the SAME output columns and writes all four outputs directly.
//   a0 = X0@W0'^T/4 (K=192), a2 = X2@W2'^T/4 (K=192),
//   P = (Xr@Wr^T - Xs@Ws^T)/2, Q = (Xr@Ws^T + Xs@Wr^T)/2   (K=384)
//   out_0=a0+a2+P, out_1=a0-a2+Q, out_2=a0+a2-P, out_3=a0-a2-Q  (+bias)

#define M_DIM 6272
#define KX    768

__device__ __half g_Xt[M_DIM * KX];   // [X0|X2|Xr|Xs], canonical k order
// per 64-o tile t (12 tiles):
//   a0: [0,147456):        t*12288 + cc*4096 + n*64   (cc 0..2, n 0..63)
//   a2: [147456,294912):   +147456, same layout
//   PQ: [294912,884736):   294912 + t*49152 + cc*8192 + n*64 (cc 0..5, n 0..127;
//       n<64 -> P col t*64+n, n>=64 -> Q col t*64+n-64)
__device__ __half g_Bp[884736];

// ---------------------------------------------------------------------------
// Prep 1: X DFT4 -> fp16. One thread per 4 c per row (301k threads).
// ---------------------------------------------------------------------------
__global__ void prep_xt_kernel(const float* __restrict__ x) {
    int idx = blockIdx.x * blockDim.x + threadIdx.x;   // 6272*48
    int b   = idx / 48;
    int c4  = (idx - b * 48) * 4;
    const float* xb = x + (size_t)b * KX;
    float4 v0 = *reinterpret_cast<const float4*>(xb + c4);
    float4 v1 = *reinterpret_cast<const float4*>(xb + 192 + c4);
    float4 v2 = *reinterpret_cast<const float4*>(xb + 384 + c4);
    float4 v3 = *reinterpret_cast<const float4*>(xb + 576 + c4);
    __half* yb = g_Xt + (size_t)b * KX + c4;
#pragma unroll
    for (int cmp = 0; cmp < 4; cmp++) {
        float c0, c1, c2, c3;
        if (cmp == 0) { c0 = v0.x+v1.x+v2.x+v3.x; c1 = v0.y+v1.y+v2.y+v3.y;
                        c2 = v0.z+v1.z+v2.z+v3.z; c3 = v0.w+v1.w+v2.w+v3.w; }
        else if (cmp == 1) { c0 = v0.x-v1.x+v2.x-v3.x; c1 = v0.y-v1.y+v2.y-v3.y;
                             c2 = v0.z-v1.z+v2.z-v3.z; c3 = v0.w-v1.w+v2.w-v3.w; }
        else if (cmp == 2) { c0 = v0.x-v2.x; c1 = v0.y-v2.y;
                             c2 = v0.z-v2.z; c3 = v0.w-v2.w; }
        else { c0 = v1.x-v3.x; c1 = v1.y-v3.y; c2 = v1.z-v3.z; c3 = v1.w-v3.w; }
        __half2 h0 = __floats2half2_rn(c0, c1);
        __half2 h1 = __floats2half2_rn(c2, c3);
        uint2 packed;
        packed.x = *reinterpret_cast<uint32_t*>(&h0);
        packed.y = *reinterpret_cast<uint32_t*>(&h1);
        *reinterpret_cast<uint2*>(yb + cmp * 192) = packed;
    }
}

// ---------------------------------------------------------------------------
// Prep 2: pack weights -> fp16 per 64-o tile.
// ---------------------------------------------------------------------------
__global__ void prep_bp_kernel(const float* __restrict__ w) {
    int idx = blockIdx.x * blockDim.x + threadIdx.x;   // 13824
    float val[64];
    __half* dst;
    if (idx < 4608) {                       // a0 / a2
        int cmp = idx / 2304;
        int rr  = idx - cmp * 2304;
        int t   = rr / 192;                 // 64-o tile
        int rem = rr - t * 192;
        int cc  = rem >> 6;                 // chunk 0..2
        int n   = rem & 63;
        int o   = t * 64 + n;
        const float* b0 = w + o * 192 + cc * 64;
        float sg = cmp ? -1.0f : 1.0f;
#pragma unroll 8
        for (int kk = 0; kk < 64; kk++) {
            float w0 = b0[kk], w1 = b0[147456 + kk];
            float w2 = b0[294912 + kk], w3 = b0[442368 + kk];
            val[kk] = 0.25f * (w0 + sg * w1 + w2 + sg * w3);
        }
        dst = g_Bp + cmp * 147456 + t * 12288 + cc * 4096 + n * 64;
    } else {                                // PQ
        int i2  = idx - 4608;               // 0..9215
        int t   = i2 / 768;
        int rem = i2 - t * 768;
        int cc  = rem >> 7;                 // chunk 0..5
        int n   = rem & 127;
        int isQ = n >> 6;
        int o   = t * 64 + (n & 63);
        int ccx = (cc < 3 ? cc : cc - 3) * 64;
        const float* b0 = w + o * 192 + ccx;
#pragma unroll 8
        for (int kk = 0; kk < 64; kk++) {
            float d02 = b0[kk] - b0[294912 + kk];           // Wr-ish
            float d13 = b0[147456 + kk] - b0[442368 + kk];  // Ws-ish
            float pv, qv;
            if (cc < 3) { pv = 0.5f * d02;  qv = 0.5f * d13; }   // Xr rows
            else        { pv = -0.5f * d13; qv = 0.5f * d02; }   // Xs rows
            val[kk] = isQ ? qv : pv;
        }
        dst = g_Bp + 294912 + t * 49152 + cc * 8192 + n * 64;
    }
    __half h[64];
#pragma unroll
    for (int kk = 0; kk < 64; kk++) h[kk] = __float2half_rn(val[kk]);
#pragma unroll
    for (int q = 0; q < 8; q++)
        reinterpret_cast<uint4*>(dst)[q] = reinterpret_cast<const uint4*>(h)[q];
}

// ---------------------------------------------------------------------------
// Fused GEMM. Grid (12, 49), 512 threads, 3-stage cp.async (32KB/stage).
// Warp tile 16 M x 32 o; acc groups a0/a2/P/Q = 16 floats each.
// ---------------------------------------------------------------------------
#define STAGES 3
#define STG_B 32768
#define SMEM_BYTES (STAGES * STG_B)

__device__ __forceinline__ void mma_f16(float* c, uint32_t a0, uint32_t a1,
                                        uint32_t a2, uint32_t a3,
                                        uint32_t b0, uint32_t b1) {
    asm volatile(
        "mma.sync.aligned.m16n8k16.row.col.f32.f16.f16.f32 "
        "{%0,%1,%2,%3}, {%4,%5,%6,%7}, {%8,%9}, {%0,%1,%2,%3};"
        : "+f"(c[0]), "+f"(c[1]), "+f"(c[2]), "+f"(c[3])
        : "r"(a0), "r"(a1), "r"(a2), "r"(a3), "r"(b0), "r"(b1));
}
#define LDSM_X4(r0, r1, r2, r3, a) \
    asm volatile("ldmatrix.sync.aligned.m8n8.x4.shared.b16 {%0,%1,%2,%3}, [%4];" \
                 : "=r"(r0), "=r"(r1), "=r"(r2), "=r"(r3) : "r"(a))

__global__ __launch_bounds__(512)
void gemm_fused_kernel(const float* __restrict__ bias, float* __restrict__ out) {
    extern __shared__ char smem[];
    const int t   = blockIdx.x;          // 64-o tile
    const int bm  = blockIdx.y * 128;

    const int tid  = threadIdx.x;
    const int warp = tid >> 5;
    const int lane = tid & 31;
    const int g    = lane >> 2;
    const int tig  = lane & 3;
    const int wM   = (warp >> 1) * 16;   // 8 warp-rows of 16
    const int wN   = (warp & 1) * 32;    // 2 warp-cols of 32

    float aA0[4][4], aA2[4][4], aP[4][4], aQ[4][4];
#pragma unroll
    for (int ni = 0; ni < 4; ni++)
#pragma unroll
        for (int r = 0; r < 4; r++)
            { aA0[ni][r] = 0.f; aA2[ni][r] = 0.f; aP[ni][r] = 0.f; aQ[ni][r] = 0.f; }

    uint32_t sbase;
    asm("{ .reg .u64 t; cvta.to.shared.u64 t, %1; cvt.u32.u64 %0, t; }"
        : "=r"(sbase) : "l"(smem));

    // loaders: A 128 rows x 8 chunks (1024 ops, 2/thread);
    //          B light 64 rows (512 ops, 1/thread), heavy 128 rows (2/thread)
    const int rA  = tid & 127, cA = (tid >> 7) * 2;        // chunks cA, cA+1
    const int rBl = tid & 63,  cBl = tid >> 6;             // 1 chunk
    const int rBh = tid & 127, cBh = (tid >> 7) * 2;

    auto load_stage = [&](int q, int s) {
        int aofs = (q < 3) ? q * 64 : (q < 6) ? 192 + (q - 3) * 64
                                              : 384 + (q - 6) * 64;
        int bofs = (q < 3) ? t * 12288 + q * 4096
                 : (q < 6) ? 147456 + t * 12288 + (q - 3) * 4096
                           : 294912 + t * 49152 + (q - 6) * 8192;
        uint32_t ab = sbase + (uint32_t)(s * STG_B);
        uint32_t bb = ab + 16384u;
        const char* pa = reinterpret_cast<const char*>(
            g_Xt + (size_t)(bm + rA) * KX + aofs);
#pragma unroll
        for (int f = 0; f < 2; f++) {
            int c = cA + f;
            uint32_t wd = (uint32_t)(rA * 128 + ((c ^ (rA & 7)) << 4));
            asm volatile("cp.async.cg.shared.global [%0], [%1], 16;"
                         :: "r"(ab + wd), "l"(pa + c * 16));
        }
        if (q < 6) {
            const char* pb = reinterpret_cast<const char*>(g_Bp + bofs) + rBl * 128;
            uint32_t wd = (uint32_t)(rBl * 128 + ((cBl ^ (rBl & 7)) << 4));
            asm volatile("cp.async.cg.shared.global [%0], [%1], 16;"
                         :: "r"(bb + wd), "l"(pb + cBl * 16));
        } else {
            const char* pb = reinterpret_cast<const char*>(g_Bp + bofs) + rBh * 128;
#pragma unroll
            for (int f = 0; f < 2; f++) {
                int c = cBh + f;
                uint32_t wd = (uint32_t)(rBh * 128 + ((c ^ (rBh & 7)) << 4));
                asm volatile("cp.async.cg.shared.global [%0], [%1], 16;"
                             :: "r"(bb + wd), "l"(pb + c * 16));
            }
        }
    };

    // ldmatrix lane mappings (as proven in rounds 6-8)
    const int rowAl = wM + (lane & 15);
    const int chA   = lane >> 4;
    const int rowBl = (lane & 7) + ((lane >> 4) & 1) * 8;
    const int chB   = (lane >> 3) & 1;
    int rB0 = wN + rowBl, rB1 = wN + 16 + rowBl;

    auto compute_light = [&](int s, float (&acc)[4][4]) {
        uint32_t As = sbase + (uint32_t)(s * STG_B);
        uint32_t Bs = As + 16384u;
#pragma unroll
        for (int kg = 0; kg < 4; kg++) {
            uint32_t a0, a1, a2, a3;
            LDSM_X4(a0, a1, a2, a3, As + (uint32_t)(rowAl * 128
                    + (((2 * kg + chA) ^ (rowAl & 7)) << 4)));
            uint32_t bf[8];
            LDSM_X4(bf[0], bf[1], bf[2], bf[3], Bs + (uint32_t)(rB0 * 128
                    + (((2 * kg + chB) ^ (rB0 & 7)) << 4)));
            LDSM_X4(bf[4], bf[5], bf[6], bf[7], Bs + (uint32_t)(rB1 * 128
                    + (((2 * kg + chB) ^ (rB1 & 7)) << 4)));
#pragma unroll
            for (int ni = 0; ni < 4; ni++)
                mma_f16(acc[ni], a0, a1, a2, a3, bf[ni * 2], bf[ni * 2 + 1]);
        }
    };
    auto compute_heavy = [&](int s) {
        uint32_t As = sbase + (uint32_t)(s * STG_B);
        uint32_t Bs = As + 16384u;
#pragma unroll
        for (int kg = 0; kg < 4; kg++) {
            uint32_t a0, a1, a2, a3;
            LDSM_X4(a0, a1, a2, a3, As + (uint32_t)(rowAl * 128
                    + (((2 * kg + chA) ^ (rowAl & 7)) << 4)));
            uint32_t bp[8], bq[8];
            LDSM_X4(bp[0], bp[1], bp[2], bp[3], Bs + (uint32_t)(rB0 * 128
                    + (((2 * kg + chB) ^ (rB0 & 7)) << 4)));
            LDSM_X4(bp[4], bp[5], bp[6], bp[7], Bs + (uint32_t)(rB1 * 128
                    + (((2 * kg + chB) ^ (rB1 & 7)) << 4)));
            int rQ0 = 64 + rB0, rQ1 = 64 + rB1;
            LDSM_X4(bq[0], bq[1], bq[2], bq[3], Bs + (uint32_t)(rQ0 * 128
                    + (((2 * kg + chB) ^ (rQ0 & 7)) << 4)));
            LDSM_X4(bq[4], bq[5], bq[6], bq[7], Bs + (uint32_t)(rQ1 * 128
                    + (((2 * kg + chB) ^ (rQ1 & 7)) << 4)));
#pragma unroll
            for (int ni = 0; ni < 4; ni++) {
                mma_f16(aP[ni], a0, a1, a2, a3, bp[ni * 2], bp[ni * 2 + 1]);
                mma_f16(aQ[ni], a0, a1, a2, a3, bq[ni * 2], bq[ni * 2 + 1]);
            }
        }
    };

    load_stage(0, 0);
    asm volatile("cp.async.commit_group;");
    load_stage(1, 1);
    asm volatile("cp.async.commit_group;");
    asm volatile("cp.async.wait_group 1;");
    __syncthreads();

    for (int q = 0; q < 12; q++) {
        if (q + 2 < 12) load_stage(q + 2, (q + 2) % 3);
        asm volatile("cp.async.commit_group;");
        if (q < 3)      compute_light(q % 3, aA0);
        else if (q < 6) compute_light(q % 3, aA2);
        else            compute_heavy(q % 3);
        asm volatile("cp.async.wait_group 1;");
        __syncthreads();
    }

    // Fused epilogue: combine in registers, direct fp32 stores + bias.
#pragma unroll
    for (int ni = 0; ni < 4; ni++) {
        int col = t * 64 + wN + ni * 8 + 2 * tig;
        float2 bv0 = *reinterpret_cast<const float2*>(bias + col);
        float2 bv1 = *reinterpret_cast<const float2*>(bias + 768 + col);
        float2 bv2 = *reinterpret_cast<const float2*>(bias + 1536 + col);
        float2 bv3 = *reinterpret_cast<const float2*>(bias + 2304 + col);
#pragma unroll
        for (int h = 0; h < 2; h++) {
            int row = bm + wM + g + 8 * h;
            float a0x = aA0[ni][2*h], a0y = aA0[ni][2*h+1];
            float a2x = aA2[ni][2*h], a2y = aA2[ni][2*h+1];
            float px  = aP[ni][2*h],  py  = aP[ni][2*h+1];
            float qx  = aQ[ni][2*h],  qy  = aQ[ni][2*h+1];
            float sx = a0x + a2x, sy = a0y + a2y;
            float dx = a0x - a2x, dy = a0y - a2y;
            float* ob = out + (size_t)row * 3072;
            *reinterpret_cast<float2*>(ob + col) =
                make_float2(sx + px + bv0.x, sy + py + bv0.y);
            *reinterpret_cast<float2*>(ob + 768 + col) =
                make_float2(dx + qx + bv1.x, dy + qy + bv1.y);
            *reinterpret_cast<float2*>(ob + 1536 + col) =
                make_float2(sx - px + bv2.x, sy - py + bv2.y);
            *reinterpret_cast<float2*>(ob + 2304 + col) =
                make_float2(dx - qx + bv3.x, dy - qy + bv3.y);
        }
    }
}

// ---------------------------------------------------------------------------
extern "C" void kernel_launch(void* const* d_in, const int* in_sizes, int n_in,
                              void* d_out, int out_size) {
    const float* x    = (const float*)d_in[0];
    const float* w    = (const float*)d_in[1];
    const float* bias = (const float*)d_in[2];
    float* out = (float*)d_out;

    cudaFuncSetAttribute(gemm_fused_kernel,
                         cudaFuncAttributeMaxDynamicSharedMemorySize, SMEM_BYTES);

    prep_xt_kernel<<<(M_DIM * 48) / 256, 256>>>(x);     // 1176 blocks
    prep_bp_kernel<<<13824 / 128, 128>>>(w);            // 108 blocks

    dim3 grid(12, 49);
    gemm_fused_kernel<<<grid, 512, SMEM_BYTES>>>(bias, out);
}

// round 12
// speedup vs baseline: 1.3584x; 1.3584x over previous
#include <cuda_runtime.h>
#include <cuda_fp16.h>
#include <cstdint>

// HypercomplexLinear via DFT-4 diagonalization + fp16 mma.sync m16n8k16.
//   a0 = X0@W0'^T/4 (K=192), a2 = X2@W2'^T/4 (K=192),
//   P = (Xr@Wr^T - Xs@Ws^T)/2, Q = (Xr@Ws^T + Xs@Wr^T)/2   (K=384)
//   out_0=a0+a2+P, out_1=a0-a2+Q, out_2=a0+a2-P, out_3=a0-a2-Q  (+bias)
// G = [Out0|Out2|P|Q] fp16 intermediate, combine pass to fp32 out.
// (Round-8 GEMM core — proven optimum of the legacy HMMA path.)

#define M_DIM 6272
#define KX    768

__device__ __half g_Xt[M_DIM * KX];   // [X0|X2|Xr|Xs], canonical k order
// a0 tiles [0,147456): 6 x (3 chunks x 128n x 64k); a2 [147456,294912);
// PQ [294912,...): 12 x (6 chunks x 128n x 64k)  (0..5=P, 6..11=Q)
__device__ __half g_Bp[884736];
__device__ __half g_G[M_DIM * 3072];  // fp16 intermediate

// ---------------------------------------------------------------------------
// Prep 1: X DFT4 -> fp16. One thread per 4 c per row (301k threads).
// ---------------------------------------------------------------------------
__global__ void prep_xt_kernel(const float* __restrict__ x) {
    int idx = blockIdx.x * blockDim.x + threadIdx.x;   // 6272*48
    int b   = idx / 48;
    int c4  = (idx - b * 48) * 4;
    const float* xb = x + (size_t)b * KX;
    float4 v0 = *reinterpret_cast<const float4*>(xb + c4);
    float4 v1 = *reinterpret_cast<const float4*>(xb + 192 + c4);
    float4 v2 = *reinterpret_cast<const float4*>(xb + 384 + c4);
    float4 v3 = *reinterpret_cast<const float4*>(xb + 576 + c4);
    __half* yb = g_Xt + (size_t)b * KX + c4;
#pragma unroll
    for (int cmp = 0; cmp < 4; cmp++) {
        float c0, c1, c2, c3;
        if (cmp == 0) { c0 = v0.x+v1.x+v2.x+v3.x; c1 = v0.y+v1.y+v2.y+v3.y;
                        c2 = v0.z+v1.z+v2.z+v3.z; c3 = v0.w+v1.w+v2.w+v3.w; }
        else if (cmp == 1) { c0 = v0.x-v1.x+v2.x-v3.x; c1 = v0.y-v1.y+v2.y-v3.y;
                             c2 = v0.z-v1.z+v2.z-v3.z; c3 = v0.w-v1.w+v2.w-v3.w; }
        else if (cmp == 2) { c0 = v0.x-v2.x; c1 = v0.y-v2.y;
                             c2 = v0.z-v2.z; c3 = v0.w-v2.w; }
        else { c0 = v1.x-v3.x; c1 = v1.y-v3.y; c2 = v1.z-v3.z; c3 = v1.w-v3.w; }
        __half2 h0 = __floats2half2_rn(c0, c1);
        __half2 h1 = __floats2half2_rn(c2, c3);
        uint2 packed;
        packed.x = *reinterpret_cast<uint32_t*>(&h0);
        packed.y = *reinterpret_cast<uint32_t*>(&h1);
        *reinterpret_cast<uint2*>(yb + cmp * 192) = packed;
    }
}

// ---------------------------------------------------------------------------
// Prep 2: pack weights -> fp16, [n][64k] rows per chunk, canonical k order.
// ---------------------------------------------------------------------------
__global__ void prep_bp_kernel(const float* __restrict__ w) {
    int idx = blockIdx.x * blockDim.x + threadIdx.x;   // 13824
    float val[64];
    __half* dst;
    if (idx < 4608) {                       // a0 / a2
        int cmp  = idx / 2304;
        int rr   = idx - cmp * 2304;
        int tile = rr / 384;
        int rem  = rr - tile * 384;
        int cc   = rem >> 7;                // chunk 0..2
        int n    = rem & 127;
        int o    = tile * 128 + n;
        const float* b0 = w + o * 192 + cc * 64;
        float sg = cmp ? -1.0f : 1.0f;
#pragma unroll 8
        for (int kk = 0; kk < 64; kk++) {
            float w0 = b0[kk], w1 = b0[147456 + kk];
            float w2 = b0[294912 + kk], w3 = b0[442368 + kk];
            val[kk] = 0.25f * (w0 + sg * w1 + w2 + sg * w3);
        }
        dst = g_Bp + cmp * 147456 + tile * 24576 + cc * 8192 + n * 64;
    } else {                                // PQ
        int i2   = idx - 4608;
        int t12  = i2 / 768;                // 0..11
        int rem  = i2 - t12 * 768;
        int cc   = rem >> 7;                // chunk 0..5
        int n    = rem & 127;
        int isQ  = t12 >= 6;
        int o    = (t12 % 6) * 128 + n;
        int ccx  = (cc < 3 ? cc : cc - 3) * 64;
        const float* b0 = w + o * 192 + ccx;
#pragma unroll 8
        for (int kk = 0; kk < 64; kk++) {
            float d02 = b0[kk] - b0[294912 + kk];
            float d13 = b0[147456 + kk] - b0[442368 + kk];
            float pv, qv;
            if (cc < 3) { pv = 0.5f * d02;  qv = 0.5f * d13; }
            else        { pv = -0.5f * d13; qv = 0.5f * d02; }
            val[kk] = isQ ? qv : pv;
        }
        dst = g_Bp + 294912 + t12 * 49152 + cc * 8192 + n * 64;
    }
    __half h[64];
#pragma unroll
    for (int kk = 0; kk < 64; kk++) h[kk] = __float2half_rn(val[kk]);
#pragma unroll
    for (int q = 0; q < 8; q++)
        reinterpret_cast<uint4*>(dst)[q] = reinterpret_cast<const uint4*>(h)[q];
}

// ---------------------------------------------------------------------------
// fp16 GEMM with ldmatrix. CTA 128x128, K-chunk 64, 3-stage cp.async.
// 2 CTAs/SM (96KB smem each). Heavy (K=384) tiles scheduled first.
// ---------------------------------------------------------------------------
#define STAGES 3
#define STG_B 32768
#define SMEM_BYTES (STAGES * STG_B)

__device__ __forceinline__ void mma_f16(float* c, uint32_t a0, uint32_t a1,
                                        uint32_t a2, uint32_t a3,
                                        uint32_t b0, uint32_t b1) {
    asm volatile(
        "mma.sync.aligned.m16n8k16.row.col.f32.f16.f16.f32 "
        "{%0,%1,%2,%3}, {%4,%5,%6,%7}, {%8,%9}, {%0,%1,%2,%3};"
        : "+f"(c[0]), "+f"(c[1]), "+f"(c[2]), "+f"(c[3])
        : "r"(a0), "r"(a1), "r"(a2), "r"(a3), "r"(b0), "r"(b1));
}
#define LDSM_X4(r0, r1, r2, r3, a) \
    asm volatile("ldmatrix.sync.aligned.m8n8.x4.shared.b16 {%0,%1,%2,%3}, [%4];" \
                 : "=r"(r0), "=r"(r1), "=r"(r2), "=r"(r3) : "r"(a))

__global__ __launch_bounds__(256, 2)
void gemm_f16_kernel() {
    extern __shared__ char smem[];
    const int nt  = (blockIdx.x + 12) % 24;   // heavy PQ tiles (12..23) first
    const int bm  = blockIdx.y * 128;
    const int bn  = nt * 128;

    int aoff, KT;
    const __half* Bg;
    if (nt < 6)       { aoff = 0;   KT = 3; Bg = g_Bp + nt * 24576; }
    else if (nt < 12) { aoff = 192; KT = 3; Bg = g_Bp + 147456 + (nt - 6) * 24576; }
    else              { aoff = 384; KT = 6; Bg = g_Bp + 294912 + (nt - 12) * 49152; }

    const int tid  = threadIdx.x;
    const int warp = tid >> 5;
    const int lane = tid & 31;
    const int g    = lane >> 2;
    const int tig  = lane & 3;
    const int wm   = (warp & 1) * 64;
    const int wn   = (warp >> 1) * 32;

    float acc[4][4][4];
#pragma unroll
    for (int mi = 0; mi < 4; mi++)
#pragma unroll
        for (int ni = 0; ni < 4; ni++)
#pragma unroll
            for (int r = 0; r < 4; r++) acc[mi][ni][r] = 0.0f;

    // cp.async loader: 2 threads per row, 4 x 16B chunks each
    const int lrow = tid >> 1;
    const int cseg = (tid & 1) * 4;
    const int ssw  = lrow & 7;
    const char* gA = reinterpret_cast<const char*>(
        g_Xt + (size_t)(bm + lrow) * KX + aoff);
    const char* gB = reinterpret_cast<const char*>(Bg + lrow * 64);
    uint32_t sbase;
    asm("{ .reg .u64 t; cvta.to.shared.u64 t, %1; cvt.u32.u64 %0, t; }"
        : "=r"(sbase) : "l"(smem));

    auto load_stage = [&](int kt, int s) {
        uint32_t ab = sbase + (uint32_t)(s * STG_B);
        uint32_t bb = ab + 16384u;
#pragma unroll
        for (int f = 0; f < 4; f++) {
            int c = cseg + f;
            uint32_t wd = (uint32_t)(lrow * 128 + ((c ^ ssw) << 4));
            asm volatile("cp.async.cg.shared.global [%0], [%1], 16;"
                         :: "r"(ab + wd), "l"(gA + kt * 128 + c * 16));
            asm volatile("cp.async.cg.shared.global [%0], [%1], 16;"
                         :: "r"(bb + wd), "l"(gB + kt * 16384 + c * 16));
        }
    };

    // ldmatrix per-lane row mapping
    const int rowA = (lane & 7) + ((lane >> 3) & 1) * 8;
    const int chA  = lane >> 4;
    const int rowB = (lane & 7) + ((lane >> 4) & 1) * 8;
    const int chB  = (lane >> 3) & 1;
    int rA[4], rB[2];
#pragma unroll
    for (int mi = 0; mi < 4; mi++) rA[mi] = wm + mi * 16 + rowA;
#pragma unroll
    for (int n2 = 0; n2 < 2; n2++) rB[n2] = wn + n2 * 16 + rowB;

    auto compute = [&](int s) {
        uint32_t As = sbase + (uint32_t)(s * STG_B);
        uint32_t Bs = As + 16384u;
#pragma unroll
        for (int kg = 0; kg < 4; kg++) {
            uint32_t af[4][4], bf[2][4];
#pragma unroll
            for (int mi = 0; mi < 4; mi++) {
                uint32_t ad = As + (uint32_t)(rA[mi] * 128
                            + (((2 * kg + chA) ^ (rA[mi] & 7)) << 4));
                LDSM_X4(af[mi][0], af[mi][1], af[mi][2], af[mi][3], ad);
            }
#pragma unroll
            for (int n2 = 0; n2 < 2; n2++) {
                uint32_t bd = Bs + (uint32_t)(rB[n2] * 128
                            + (((2 * kg + chB) ^ (rB[n2] & 7)) << 4));
                LDSM_X4(bf[n2][0], bf[n2][1], bf[n2][2], bf[n2][3], bd);
            }
#pragma unroll
            for (int ni = 0; ni < 4; ni++) {
                uint32_t b0 = bf[ni >> 1][(ni & 1) * 2];
                uint32_t b1 = bf[ni >> 1][(ni & 1) * 2 + 1];
#pragma unroll
                for (int mi = 0; mi < 4; mi++)
                    mma_f16(acc[mi][ni], af[mi][0], af[mi][1], af[mi][2], af[mi][3],
                            b0, b1);
            }
        }
    };

    int fetch = 0;
#pragma unroll
    for (int s = 0; s < STAGES - 1; s++) {
        if (fetch < KT) load_stage(fetch, s);
        asm volatile("cp.async.commit_group;");
        fetch++;
    }
    asm volatile("cp.async.wait_group %0;" :: "n"(STAGES - 2));
    __syncthreads();

    for (int kt = 0; kt < KT; kt++) {
        if (fetch < KT) load_stage(fetch, fetch % STAGES);
        asm volatile("cp.async.commit_group;");
        fetch++;
        compute(kt % STAGES);
        asm volatile("cp.async.wait_group %0;" :: "n"(STAGES - 2));
        __syncthreads();
    }

    // Epilogue: acc -> fp16 smem tile (row stride 136) -> coalesced stores
    __half* sg = reinterpret_cast<__half*>(smem);
#pragma unroll
    for (int mi = 0; mi < 4; mi++) {
        int row0 = wm + mi * 16 + g;
#pragma unroll
        for (int ni = 0; ni < 4; ni++) {
            int col = wn + ni * 8 + 2 * tig;
            *reinterpret_cast<__half2*>(sg + row0 * 136 + col) =
                __floats2half2_rn(acc[mi][ni][0], acc[mi][ni][1]);
            *reinterpret_cast<__half2*>(sg + (row0 + 8) * 136 + col) =
                __floats2half2_rn(acc[mi][ni][2], acc[mi][ni][3]);
        }
    }
    __syncthreads();
#pragma unroll
    for (int i = 0; i < 8; i++) {
        int linear = tid + 256 * i;
        int row = linear >> 4;
        int q   = linear & 15;
        uint4 v = *reinterpret_cast<const uint4*>(sg + row * 136 + q * 8);
        *reinterpret_cast<uint4*>(g_G + (size_t)(bm + row) * 3072 + bn + q * 8) = v;
    }
}

// ---------------------------------------------------------------------------
// Combine: fp16 G -> fp32 out with bias. One thread per (b, 2 o) — 2.4M thr.
// ---------------------------------------------------------------------------
__global__ void combine_kernel(const float* __restrict__ bias,
                               float* __restrict__ out) {
    int idx = blockIdx.x * blockDim.x + threadIdx.x;   // 6272*384
    int b  = idx / 384;
    int o2 = (idx - b * 384) * 2;
    const __half* Gb = g_G + (size_t)b * 3072;
    __half2 a0 = *reinterpret_cast<const __half2*>(Gb + o2);
    __half2 a2 = *reinterpret_cast<const __half2*>(Gb + 768 + o2);
    __half2 p  = *reinterpret_cast<const __half2*>(Gb + 1536 + o2);
    __half2 q  = *reinterpret_cast<const __half2*>(Gb + 2304 + o2);

    float2 fa0 = __half22float2(a0);
    float2 fa2 = __half22float2(a2);
    float2 fp  = __half22float2(p);
    float2 fq  = __half22float2(q);
    float sx = fa0.x + fa2.x, sy = fa0.y + fa2.y;
    float dx = fa0.x - fa2.x, dy = fa0.y - fa2.y;

    const float2 bv0 = *reinterpret_cast<const float2*>(bias + o2);
    const float2 bv1 = *reinterpret_cast<const float2*>(bias + 768 + o2);
    const float2 bv2 = *reinterpret_cast<const float2*>(bias + 1536 + o2);
    const float2 bv3 = *reinterpret_cast<const float2*>(bias + 2304 + o2);

    float* ob = out + (size_t)b * 3072 + o2;
    *reinterpret_cast<float2*>(ob)        = make_float2(sx + fp.x + bv0.x, sy + fp.y + bv0.y);
    *reinterpret_cast<float2*>(ob + 768)  = make_float2(dx + fq.x + bv1.x, dy + fq.y + bv1.y);
    *reinterpret_cast<float2*>(ob + 1536) = make_float2(sx - fp.x + bv2.x, sy - fp.y + bv2.y);
    *reinterpret_cast<float2*>(ob + 2304) = make_float2(dx - fq.x + bv3.x, dy - fq.y + bv3.y);
}

// ---------------------------------------------------------------------------
extern "C" void kernel_launch(void* const* d_in, const int* in_sizes, int n_in,
                              void* d_out, int out_size) {
    const float* x    = (const float*)d_in[0];
    const float* w    = (const float*)d_in[1];
    const float* bias = (const float*)d_in[2];
    float* out = (float*)d_out;

    cudaFuncSetAttribute(gemm_f16_kernel,
                         cudaFuncAttributeMaxDynamicSharedMemorySize, SMEM_BYTES);

    prep_xt_kernel<<<(M_DIM * 48) / 256, 256>>>(x);     // 1176 blocks
    prep_bp_kernel<<<13824 / 128, 128>>>(w);            // 108 blocks

    dim3 grid(24, 49);
    gemm_f16_kernel<<<grid, 256, SMEM_BYTES>>>();

    combine_kernel<<<(M_DIM * 384) / 256, 256>>>(bias, out);  // 9408 blocks
}